// round 3
// baseline (speedup 1.0000x reference)
#include <cuda_runtime.h>
#include <cstdint>

#define M_DIM 8192
#define K_DIM 4096
#define N_DIM 16384

// Scratch: device globals (allocation-free rule)
static __device__ __align__(16) signed char g_qx[(size_t)M_DIM * K_DIM];   // 32 MB
static __device__ __align__(16) signed char g_wq[(size_t)N_DIM * K_DIM];   // 64 MB
static __device__ float g_sx[M_DIM];

// ---------------------------------------------------------------------------
// Kernel 1: per-row absmax + symmetric int8 quantization (bit-exact vs ref).
// ---------------------------------------------------------------------------
__global__ void quant_rows_kernel(const float* __restrict__ x) {
    int row = blockIdx.x;
    int t = threadIdx.x;
    const float4* xr = reinterpret_cast<const float4*>(x + (size_t)row * K_DIM);
    float4 v[4];
    float amax = 0.0f;
#pragma unroll
    for (int i = 0; i < 4; i++) {
        v[i] = xr[t + i * 256];
        amax = fmaxf(amax, fabsf(v[i].x));
        amax = fmaxf(amax, fabsf(v[i].y));
        amax = fmaxf(amax, fabsf(v[i].z));
        amax = fmaxf(amax, fabsf(v[i].w));
    }
    __shared__ float red[8];
    __shared__ float s_scale;
#pragma unroll
    for (int o = 16; o > 0; o >>= 1)
        amax = fmaxf(amax, __shfl_xor_sync(0xffffffffu, amax, o));
    if ((t & 31) == 0) red[t >> 5] = amax;
    __syncthreads();
    if (t == 0) {
        float m = red[0];
#pragma unroll
        for (int i = 1; i < 8; i++) m = fmaxf(m, red[i]);
        float sc = m / 127.0f;
        s_scale = sc;
        g_sx[row] = sc;
    }
    __syncthreads();
    float scale = s_scale;
    char4* qr = reinterpret_cast<char4*>(g_qx + (size_t)row * K_DIM);
#pragma unroll
    for (int i = 0; i < 4; i++) {
        char4 q;
        q.x = (signed char)__float2int_rn(v[i].x / scale);
        q.y = (signed char)__float2int_rn(v[i].y / scale);
        q.z = (signed char)__float2int_rn(v[i].z / scale);
        q.w = (signed char)__float2int_rn(v[i].w / scale);
        qr[t + i * 256] = q;
    }
}

// ---------------------------------------------------------------------------
// Kernel 2: repack int32 weights into int8.
// ---------------------------------------------------------------------------
__global__ void convert_w_kernel(const int4* __restrict__ w) {
    int idx = blockIdx.x * blockDim.x + threadIdx.x;
    int4 v = w[idx];
    char4 q;
    q.x = (signed char)v.x;
    q.y = (signed char)v.y;
    q.z = (signed char)v.z;
    q.w = (signed char)v.w;
    reinterpret_cast<char4*>(g_wq)[idx] = q;
}

// ---------------------------------------------------------------------------
// Kernel 3: IMMA GEMM. CTA tile 128x256x64, 8 warps, warp tile 64x64.
// ldmatrix.x4 fragment loads from 80B-padded smem rows (conflict-free),
// 4-stage cp.async pipeline, fused dequant epilogue.
// ---------------------------------------------------------------------------
#define BMg 128
#define BNg 256
#define BKg 64
#define SROW 80
#define NSTAGE 4
#define STA (BMg * SROW)                 // 10240
#define STB (BNg * SROW)                 // 20480
#define STAGE_BYTES (STA + STB)          // 30720
#define NK (K_DIM / BKg)                 // 64
#define SMEM_TOTAL (NSTAGE * STAGE_BYTES + 128)

__device__ __forceinline__ uint32_t smem_u32(const void* p) {
    uint32_t a;
    asm("{ .reg .u64 t; cvta.to.shared.u64 t, %1; cvt.u32.u64 %0, t; }" : "=r"(a) : "l"(p));
    return a;
}
__device__ __forceinline__ void cp16(uint32_t s, const void* g) {
    asm volatile("cp.async.cg.shared.global [%0], [%1], 16;" :: "r"(s), "l"(g));
}
__device__ __forceinline__ void ldm_x4(uint32_t& r0, uint32_t& r1, uint32_t& r2,
                                       uint32_t& r3, uint32_t addr) {
    asm volatile("ldmatrix.sync.aligned.m8n8.x4.shared.b16 {%0,%1,%2,%3}, [%4];"
                 : "=r"(r0), "=r"(r1), "=r"(r2), "=r"(r3) : "r"(addr));
}

__global__ __launch_bounds__(256, 1) void gemm_imma_kernel(const float* __restrict__ wscale,
                                                           const float* __restrict__ bias,
                                                           float* __restrict__ out) {
    extern __shared__ char smem[];
    uint32_t sbase = smem_u32(smem);
    sbase = (sbase + 127u) & ~127u;

    const int t = threadIdx.x;
    const int wid = t >> 5;
    const int lane = t & 31;
    const int warpM = wid & 1;            // 2 warps along M (64 each)
    const int warpN = wid >> 1;           // 4 warps along N (64 each)

    // tile decode with L2 group swizzle: tiles_m=64, tiles_n=64, GM=8
    int gid = blockIdx.x;
    int grp = gid >> 9;                   // / (8*64)
    int rem = gid & 511;
    int tm = grp * 8 + (rem & 7);
    int tn = rem >> 3;

    const signed char* gA = g_qx + (size_t)(tm * BMg) * K_DIM;
    const signed char* gB = g_wq + (size_t)(tn * BNg) * K_DIM;

    auto load_stage = [&](int buf, int kt) {
        uint32_t sA = sbase + buf * STAGE_BYTES;
        uint32_t sB = sA + STA;
        int koff = kt * BKg;
#pragma unroll
        for (int i = 0; i < 2; i++) {                 // A: 512 16B chunks
            int c = t + i * 256;
            int row = c >> 2, col = (c & 3) * 16;
            cp16(sA + row * SROW + col, gA + (size_t)row * K_DIM + koff + col);
        }
#pragma unroll
        for (int i = 0; i < 4; i++) {                 // B: 1024 16B chunks
            int c = t + i * 256;
            int row = c >> 2, col = (c & 3) * 16;
            cp16(sB + row * SROW + col, gB + (size_t)row * K_DIM + koff + col);
        }
        asm volatile("cp.async.commit_group;");
    };

    int acc[4][8][4];
#pragma unroll
    for (int mf = 0; mf < 4; mf++)
#pragma unroll
        for (int nf = 0; nf < 8; nf++)
#pragma unroll
            for (int i = 0; i < 4; i++) acc[mf][nf][i] = 0;

    // prologue: 3 stages in flight
#pragma unroll
    for (int s = 0; s < NSTAGE - 1; s++) load_stage(s, s);

    // ldmatrix lane addressing
    const int seg = lane >> 3;            // 0..3 (matrix id)
    const int lrow = lane & 7;
    const int a_row = warpM * 64 + (seg & 1) * 8 + lrow;   // + mf*16
    const int b_row = warpN * 64 + (seg & 1) * 8 + lrow;   // + nf2*16
    const int m_col = (seg >> 1) * 16;                     // + ks*32

    for (int kt = 0; kt < NK; kt++) {
        asm volatile("cp.async.wait_group 2;");
        __syncthreads();
        int nk = kt + NSTAGE - 1;
        if (nk < NK) load_stage(nk & (NSTAGE - 1), nk);
        else asm volatile("cp.async.commit_group;");

        uint32_t sA = sbase + (kt & (NSTAGE - 1)) * STAGE_BYTES;
        uint32_t sB = sA + STA;

#pragma unroll
        for (int ks = 0; ks < 2; ks++) {
            uint32_t a[4][4], b[8][2];
#pragma unroll
            for (int mf = 0; mf < 4; mf++)
                ldm_x4(a[mf][0], a[mf][1], a[mf][2], a[mf][3],
                       sA + (a_row + mf * 16) * SROW + m_col + ks * 32);
#pragma unroll
            for (int nf2 = 0; nf2 < 4; nf2++) {
                uint32_t r0, r1, r2, r3;
                ldm_x4(r0, r1, r2, r3,
                       sB + (b_row + nf2 * 16) * SROW + m_col + ks * 32);
                b[nf2 * 2][0] = r0; b[nf2 * 2][1] = r2;
                b[nf2 * 2 + 1][0] = r1; b[nf2 * 2 + 1][1] = r3;
            }
#pragma unroll
            for (int mf = 0; mf < 4; mf++)
#pragma unroll
                for (int nf = 0; nf < 8; nf++)
                    asm volatile(
                        "mma.sync.aligned.m16n8k32.row.col.s32.s8.s8.s32 "
                        "{%0,%1,%2,%3}, {%4,%5,%6,%7}, {%8,%9}, {%0,%1,%2,%3};\n"
                        : "+r"(acc[mf][nf][0]), "+r"(acc[mf][nf][1]),
                          "+r"(acc[mf][nf][2]), "+r"(acc[mf][nf][3])
                        : "r"(a[mf][0]), "r"(a[mf][1]), "r"(a[mf][2]), "r"(a[mf][3]),
                          "r"(b[nf][0]), "r"(b[nf][1]));
        }
    }

    // epilogue: dequant + bias
    const int tig = lane & 3;
    const int gID = lane >> 2;
#pragma unroll
    for (int mf = 0; mf < 4; mf++) {
        int r0 = tm * BMg + warpM * 64 + mf * 16 + gID;
        float sx0 = g_sx[r0];
        float sx1 = g_sx[r0 + 8];
        float* o0 = out + (size_t)r0 * N_DIM + tn * BNg;
        float* o1 = o0 + (size_t)8 * N_DIM;
#pragma unroll
        for (int nf = 0; nf < 8; nf++) {
            int c = warpN * 64 + nf * 8 + tig * 2;
            float w0 = __ldg(wscale + tn * BNg + c);
            float w1 = __ldg(wscale + tn * BNg + c + 1);
            float b0 = __ldg(bias + tn * BNg + c);
            float b1 = __ldg(bias + tn * BNg + c + 1);
            float2 v0, v1;
            v0.x = (float)acc[mf][nf][0] * sx0 * w0 + b0;
            v0.y = (float)acc[mf][nf][1] * sx0 * w1 + b1;
            v1.x = (float)acc[mf][nf][2] * sx1 * w0 + b0;
            v1.y = (float)acc[mf][nf][3] * sx1 * w1 + b1;
            *(float2*)(o0 + c) = v0;
            *(float2*)(o1 + c) = v1;
        }
    }
}

// ---------------------------------------------------------------------------
extern "C" void kernel_launch(void* const* d_in, const int* in_sizes, int n_in,
                              void* d_out, int out_size) {
    (void)in_sizes; (void)n_in; (void)out_size;
    const float* x      = (const float*)d_in[0];
    const int*   wq     = (const int*)d_in[1];
    const float* wscale = (const float*)d_in[2];
    const float* bias   = (const float*)d_in[3];
    float* out = (float*)d_out;

    quant_rows_kernel<<<M_DIM, 256>>>(x);

    int conv_blocks = (N_DIM / 4) * (K_DIM / 256);
    convert_w_kernel<<<conv_blocks, 256>>>((const int4*)wq);

    cudaFuncSetAttribute(gemm_imma_kernel, cudaFuncAttributeMaxDynamicSharedMemorySize,
                         SMEM_TOTAL);
    int gemm_blocks = (M_DIM / BMg) * (N_DIM / BNg);   // 64 * 64 = 4096
    gemm_imma_kernel<<<gemm_blocks, 256, SMEM_TOTAL>>>(wscale, bias, out);
}

// round 4
// speedup vs baseline: 1.0672x; 1.0672x over previous
#include <cuda_runtime.h>
#include <cstdint>

#define M_DIM 8192
#define K_DIM 4096
#define N_DIM 16384

#define BM 128
#define BN 256
#define BK 128
#define NKT (K_DIM / BK)          // 32
#define NS 4
#define STG_A (BM * BK)           // 16384
#define STG_B (BN * BK)           // 32768
#define STG (STG_A + STG_B)       // 49152
#define SMEM_TOTAL (NS * STG + 1024 + 64)

// Tiled, pre-swizzled operand images (device globals; allocation-free rule)
static __device__ __align__(128) signed char g_qa[(size_t)M_DIM * K_DIM];  // 32 MB
static __device__ __align__(128) signed char g_wb[(size_t)N_DIM * K_DIM];  // 64 MB
static __device__ float g_sx[M_DIM];

// ---------------------------------------------------------------------------
// Kernel 1: per-row absmax + int8 quantization, writing the tile-major
// SW128-swizzled image g_qa[tm][kt] (16KB blocks of 128 rows x 128B).
// ---------------------------------------------------------------------------
__global__ void quant_rows_kernel(const float* __restrict__ x) {
    int row = blockIdx.x;
    int t = threadIdx.x;
    const float4* xr = reinterpret_cast<const float4*>(x + (size_t)row * K_DIM);
    float4 v[4];
    float amax = 0.0f;
#pragma unroll
    for (int i = 0; i < 4; i++) {
        v[i] = xr[t * 4 + i];                    // 16 consecutive floats / thread
        amax = fmaxf(amax, fabsf(v[i].x));
        amax = fmaxf(amax, fabsf(v[i].y));
        amax = fmaxf(amax, fabsf(v[i].z));
        amax = fmaxf(amax, fabsf(v[i].w));
    }
    __shared__ float red[8];
    __shared__ float s_scale;
#pragma unroll
    for (int o = 16; o > 0; o >>= 1)
        amax = fmaxf(amax, __shfl_xor_sync(0xffffffffu, amax, o));
    if ((t & 31) == 0) red[t >> 5] = amax;
    __syncthreads();
    if (t == 0) {
        float m = red[0];
#pragma unroll
        for (int i = 1; i < 8; i++) m = fmaxf(m, red[i]);
        float sc = m / 127.0f;                   // exact IEEE div, matches ref
        s_scale = sc;
        g_sx[row] = sc;
    }
    __syncthreads();
    float scale = s_scale;

    // quantize the 16 values this thread owns (elements 16t..16t+15)
    union { signed char c[16]; int4 i4; } q;
#pragma unroll
    for (int i = 0; i < 4; i++) {
        q.c[i * 4 + 0] = (signed char)__float2int_rn(v[i].x / scale);
        q.c[i * 4 + 1] = (signed char)__float2int_rn(v[i].y / scale);
        q.c[i * 4 + 2] = (signed char)__float2int_rn(v[i].z / scale);
        q.c[i * 4 + 3] = (signed char)__float2int_rn(v[i].w / scale);
    }
    int tm = row >> 7, lrow = row & 127;
    int kt = t >> 3, ch = t & 7;
    size_t dst = ((size_t)(tm * NKT + kt) << 14) + (size_t)lrow * 128 +
                 ((size_t)(ch ^ (lrow & 7)) << 4);
    *reinterpret_cast<int4*>(g_qa + dst) = q.i4;
}

// ---------------------------------------------------------------------------
// Kernel 2: int32 weights -> int8, writing tile-major swizzled image
// g_wb[tn][kt] (32KB blocks of 256 rows x 128B). One block per weight row.
// ---------------------------------------------------------------------------
__global__ void convert_w_kernel(const int* __restrict__ w) {
    int n = blockIdx.x;
    int t = threadIdx.x;                         // chunk id 0..255
    const int4* wr = reinterpret_cast<const int4*>(w + (size_t)n * K_DIM);
    union { signed char c[16]; int4 i4; } q;
#pragma unroll
    for (int i = 0; i < 4; i++) {
        int4 v = wr[t * 4 + i];
        q.c[i * 4 + 0] = (signed char)v.x;
        q.c[i * 4 + 1] = (signed char)v.y;
        q.c[i * 4 + 2] = (signed char)v.z;
        q.c[i * 4 + 3] = (signed char)v.w;
    }
    int tn = n >> 8, lrow = n & 255;
    int kt = t >> 3, ch = t & 7;
    size_t dst = ((size_t)(tn * NKT + kt) << 15) + (size_t)lrow * 128 +
                 ((size_t)(ch ^ (lrow & 7)) << 4);
    *reinterpret_cast<int4*>(g_wb + dst) = q.i4;
}

// ---------------------------------------------------------------------------
// Kernel 3: IMMA GEMM fed by cp.async.bulk (2 bulk ops per stage).
// CTA tile 128x256x128, 8 warps (warp tile 64x64), 4-stage mbarrier pipeline.
// ---------------------------------------------------------------------------
__device__ __forceinline__ uint32_t smem_u32(const void* p) {
    uint32_t a;
    asm("{ .reg .u64 t; cvta.to.shared.u64 t, %1; cvt.u32.u64 %0, t; }" : "=r"(a) : "l"(p));
    return a;
}
__device__ __forceinline__ void mbar_init(uint32_t a, uint32_t c) {
    asm volatile("mbarrier.init.shared.b64 [%0], %1;" :: "r"(a), "r"(c) : "memory");
}
__device__ __forceinline__ void mbar_expect_tx(uint32_t a, uint32_t tx) {
    asm volatile("mbarrier.arrive.expect_tx.shared::cta.b64 _, [%0], %1;"
                 :: "r"(a), "r"(tx) : "memory");
}
__device__ __forceinline__ void bulk_g2s(uint32_t dst, const void* src, uint32_t bytes,
                                         uint32_t mbar) {
    asm volatile(
        "cp.async.bulk.shared::cta.global.mbarrier::complete_tx::bytes [%0], [%1], %2, [%3];"
        :: "r"(dst), "l"(src), "r"(bytes), "r"(mbar) : "memory");
}
__device__ __forceinline__ void mbar_wait(uint32_t a, uint32_t ph) {
    asm volatile(
        "{\n .reg .pred P;\n"
        "WL_%=:\n"
        " mbarrier.try_wait.parity.acquire.cta.shared::cta.b64 P, [%0], %1;\n"
        " @P bra.uni WD_%=;\n"
        " bra.uni WL_%=;\n"
        "WD_%=:\n}" :: "r"(a), "r"(ph) : "memory");
}
__device__ __forceinline__ void ldm_x4(uint32_t& r0, uint32_t& r1, uint32_t& r2,
                                       uint32_t& r3, uint32_t addr) {
    asm volatile("ldmatrix.sync.aligned.m8n8.x4.shared.b16 {%0,%1,%2,%3}, [%4];"
                 : "=r"(r0), "=r"(r1), "=r"(r2), "=r"(r3) : "r"(addr));
}

__global__ __launch_bounds__(256, 1) void gemm_imma_kernel(const float* __restrict__ wscale,
                                                           const float* __restrict__ bias,
                                                           float* __restrict__ out) {
    extern __shared__ char smem[];
    uint32_t raw = smem_u32(smem);
    uint32_t sbase = (raw + 1023u) & ~1023u;
    uint32_t barr = sbase + NS * STG;            // NS mbarriers (8B each)

    const int t = threadIdx.x;
    const int wid = t >> 5;
    const int lane = t & 31;
    const int warpM = wid & 1;                   // 2 warps along M
    const int warpN = wid >> 1;                  // 4 warps along N

    // tile decode with L2 group swizzle: tiles_m=64, tiles_n=64, GM=8
    int gid = blockIdx.x;
    int grp = gid >> 9;
    int rem = gid & 511;
    int tm = grp * 8 + (rem & 7);
    int tn = rem >> 3;

    const signed char* gA = g_qa + ((size_t)tm * NKT << 14);
    const signed char* gB = g_wb + ((size_t)tn * NKT << 15);

    if (t == 0) {
#pragma unroll
        for (int s = 0; s < NS; s++) mbar_init(barr + 8 * s, 1);
    }
    __syncthreads();

    auto issue = [&](int buf, int kt) {
        uint32_t mb = barr + 8 * buf;
        mbar_expect_tx(mb, STG);
        bulk_g2s(sbase + buf * STG,          gA + ((size_t)kt << 14), STG_A, mb);
        bulk_g2s(sbase + buf * STG + STG_A,  gB + ((size_t)kt << 15), STG_B, mb);
    };

    if (t == 0) {
#pragma unroll
        for (int s = 0; s < NS - 1; s++) issue(s, s);
    }

    int acc[4][8][4];
#pragma unroll
    for (int mf = 0; mf < 4; mf++)
#pragma unroll
        for (int nf = 0; nf < 8; nf++)
#pragma unroll
            for (int i = 0; i < 4; i++) acc[mf][nf][i] = 0;

    const int seg = lane >> 3;                   // matrix id 0..3
    const int lrow = lane & 7;
    const int a_rb = warpM * 64 + (seg & 1) * 8 + lrow;   // + mf*16
    const int b_rb = warpN * 64 + (seg & 1) * 8 + lrow;   // + nf2*16
    const int cseg = seg >> 1;                   // chunk within ks: + 2*ks

    for (int kt = 0; kt < NKT; kt++) {
        int s = kt & (NS - 1);
        mbar_wait(barr + 8 * s, (kt >> 2) & 1);

        uint32_t sA = sbase + s * STG;
        uint32_t sB = sA + STG_A;

#pragma unroll
        for (int ks = 0; ks < 4; ks++) {
            const int chunk = cseg + 2 * ks;
            uint32_t a[4][4], b[8][2];
#pragma unroll
            for (int mf = 0; mf < 4; mf++) {
                int r = a_rb + mf * 16;
                ldm_x4(a[mf][0], a[mf][1], a[mf][2], a[mf][3],
                       sA + r * 128 + ((chunk ^ (r & 7)) << 4));
            }
#pragma unroll
            for (int nf2 = 0; nf2 < 4; nf2++) {
                int r = b_rb + nf2 * 16;
                uint32_t r0, r1, r2, r3;
                ldm_x4(r0, r1, r2, r3, sB + r * 128 + ((chunk ^ (r & 7)) << 4));
                b[nf2 * 2][0] = r0; b[nf2 * 2][1] = r2;
                b[nf2 * 2 + 1][0] = r1; b[nf2 * 2 + 1][1] = r3;
            }
#pragma unroll
            for (int mf = 0; mf < 4; mf++)
#pragma unroll
                for (int nf = 0; nf < 8; nf++)
                    asm volatile(
                        "mma.sync.aligned.m16n8k32.row.col.s32.s8.s8.s32 "
                        "{%0,%1,%2,%3}, {%4,%5,%6,%7}, {%8,%9}, {%0,%1,%2,%3};\n"
                        : "+r"(acc[mf][nf][0]), "+r"(acc[mf][nf][1]),
                          "+r"(acc[mf][nf][2]), "+r"(acc[mf][nf][3])
                        : "r"(a[mf][0]), "r"(a[mf][1]), "r"(a[mf][2]), "r"(a[mf][3]),
                          "r"(b[nf][0]), "r"(b[nf][1]));
        }

        __syncthreads();
        int nk = kt + NS - 1;
        if (t == 0 && nk < NKT) issue(nk & (NS - 1), nk);
    }

    // epilogue: dequant + bias (layout identical to verified R3 epilogue)
    const int tig = lane & 3;
    const int gID = lane >> 2;
#pragma unroll
    for (int mf = 0; mf < 4; mf++) {
        int r0 = tm * BM + warpM * 64 + mf * 16 + gID;
        float sx0 = g_sx[r0];
        float sx1 = g_sx[r0 + 8];
        float* o0 = out + (size_t)r0 * N_DIM + tn * BN;
        float* o1 = o0 + (size_t)8 * N_DIM;
#pragma unroll
        for (int nf = 0; nf < 8; nf++) {
            int c = warpN * 64 + nf * 8 + tig * 2;
            float w0 = __ldg(wscale + tn * BN + c);
            float w1 = __ldg(wscale + tn * BN + c + 1);
            float b0 = __ldg(bias + tn * BN + c);
            float b1 = __ldg(bias + tn * BN + c + 1);
            float2 v0, v1;
            v0.x = (float)acc[mf][nf][0] * sx0 * w0 + b0;
            v0.y = (float)acc[mf][nf][1] * sx0 * w1 + b1;
            v1.x = (float)acc[mf][nf][2] * sx1 * w0 + b0;
            v1.y = (float)acc[mf][nf][3] * sx1 * w1 + b1;
            *(float2*)(o0 + c) = v0;
            *(float2*)(o1 + c) = v1;
        }
    }
}

// ---------------------------------------------------------------------------
extern "C" void kernel_launch(void* const* d_in, const int* in_sizes, int n_in,
                              void* d_out, int out_size) {
    (void)in_sizes; (void)n_in; (void)out_size;
    const float* x      = (const float*)d_in[0];
    const int*   wq     = (const int*)d_in[1];
    const float* wscale = (const float*)d_in[2];
    const float* bias   = (const float*)d_in[3];
    float* out = (float*)d_out;

    quant_rows_kernel<<<M_DIM, 256>>>(x);
    convert_w_kernel<<<N_DIM, 256>>>(wq);

    cudaFuncSetAttribute(gemm_imma_kernel, cudaFuncAttributeMaxDynamicSharedMemorySize,
                         SMEM_TOTAL);
    int gemm_blocks = (M_DIM / BM) * (N_DIM / BN);   // 4096
    gemm_imma_kernel<<<gemm_blocks, 256, SMEM_TOTAL>>>(wscale, bias, out);
}

// round 5
// speedup vs baseline: 2.8727x; 2.6920x over previous
#include <cuda_runtime.h>
#include <cuda_bf16.h>
#include <cstdint>

#define M_DIM 8192
#define K_DIM 4096
#define N_DIM 16384

#define BM 128
#define BN 256
#define BKE 64                     // K elements per stage (bf16) = 128B rows
#define NKT (K_DIM / BKE)          // 64
#define NS 4
#define STG_A (BM * 128)           // 16384 bytes
#define STG_B (BN * 128)           // 32768 bytes
#define STG (STG_A + STG_B)        // 49152
#define SMEM_TOTAL (NS * STG + 1024 + 64)

// Tiled, pre-swizzled bf16 operand images (device globals; allocation-free rule)
static __device__ __align__(128) __nv_bfloat16 g_qa[(size_t)M_DIM * K_DIM];  // 64 MB
static __device__ __align__(128) __nv_bfloat16 g_wb[(size_t)N_DIM * K_DIM];  // 128 MB
static __device__ float g_sx[M_DIM];

// ---------------------------------------------------------------------------
// Kernel 1: per-row absmax + int8 quantization -> bf16 (exact for |q|<=127),
// written as tile-major swizzled image: g_qa blocks [tm][kt] of 128 rows x
// 128 bytes (64 bf16), 16B chunks XOR-swizzled by row.
// ---------------------------------------------------------------------------
__global__ void quant_rows_kernel(const float* __restrict__ x) {
    int row = blockIdx.x;
    int t = threadIdx.x;
    const float4* xr = reinterpret_cast<const float4*>(x + (size_t)row * K_DIM);
    float4 v[4];
    float amax = 0.0f;
#pragma unroll
    for (int i = 0; i < 4; i++) {
        v[i] = xr[t * 4 + i];                    // 16 consecutive floats / thread
        amax = fmaxf(amax, fabsf(v[i].x));
        amax = fmaxf(amax, fabsf(v[i].y));
        amax = fmaxf(amax, fabsf(v[i].z));
        amax = fmaxf(amax, fabsf(v[i].w));
    }
    __shared__ float red[8];
    __shared__ float s_scale;
#pragma unroll
    for (int o = 16; o > 0; o >>= 1)
        amax = fmaxf(amax, __shfl_xor_sync(0xffffffffu, amax, o));
    if ((t & 31) == 0) red[t >> 5] = amax;
    __syncthreads();
    if (t == 0) {
        float m = red[0];
#pragma unroll
        for (int i = 1; i < 8; i++) m = fmaxf(m, red[i]);
        float sc = m / 127.0f;                   // exact IEEE div, matches ref
        s_scale = sc;
        g_sx[row] = sc;
    }
    __syncthreads();
    float scale = s_scale;

    union { __nv_bfloat16 h[16]; int4 i4[2]; } q;
#pragma unroll
    for (int i = 0; i < 4; i++) {
        q.h[i * 4 + 0] = __float2bfloat16_rn((float)__float2int_rn(v[i].x / scale));
        q.h[i * 4 + 1] = __float2bfloat16_rn((float)__float2int_rn(v[i].y / scale));
        q.h[i * 4 + 2] = __float2bfloat16_rn((float)__float2int_rn(v[i].z / scale));
        q.h[i * 4 + 3] = __float2bfloat16_rn((float)__float2int_rn(v[i].w / scale));
    }
    int tm = row >> 7, lrow = row & 127;
    int kt = t >> 2;                              // 4 threads per 64-elem ktile
    int ch0 = (t & 3) * 2;
    char* blk = (char*)g_qa + (((size_t)tm * NKT + kt) << 14) + (size_t)lrow * 128;
    *reinterpret_cast<int4*>(blk + (((ch0)     ^ (lrow & 7)) << 4)) = q.i4[0];
    *reinterpret_cast<int4*>(blk + (((ch0 + 1) ^ (lrow & 7)) << 4)) = q.i4[1];
}

// ---------------------------------------------------------------------------
// Kernel 2: int32 weights -> bf16 (exact), tile-major swizzled image:
// g_wb blocks [tn][kt] of 256 rows x 128 bytes.
// ---------------------------------------------------------------------------
__global__ void convert_w_kernel(const int* __restrict__ w) {
    int n = blockIdx.x;
    int t = threadIdx.x;
    const int4* wr = reinterpret_cast<const int4*>(w + (size_t)n * K_DIM);
    union { __nv_bfloat16 h[16]; int4 i4[2]; } q;
#pragma unroll
    for (int i = 0; i < 4; i++) {
        int4 v = wr[t * 4 + i];
        q.h[i * 4 + 0] = __float2bfloat16_rn((float)v.x);
        q.h[i * 4 + 1] = __float2bfloat16_rn((float)v.y);
        q.h[i * 4 + 2] = __float2bfloat16_rn((float)v.z);
        q.h[i * 4 + 3] = __float2bfloat16_rn((float)v.w);
    }
    int tn = n >> 8, lrow = n & 255;
    int kt = t >> 2;
    int ch0 = (t & 3) * 2;
    char* blk = (char*)g_wb + (((size_t)tn * NKT + kt) << 15) + (size_t)lrow * 128;
    *reinterpret_cast<int4*>(blk + (((ch0)     ^ (lrow & 7)) << 4)) = q.i4[0];
    *reinterpret_cast<int4*>(blk + (((ch0 + 1) ^ (lrow & 7)) << 4)) = q.i4[1];
}

// ---------------------------------------------------------------------------
// Kernel 3: bf16 HMMA GEMM (f32 accum, exact on integer inputs), fed by
// cp.async.bulk. CTA tile 128x256, 8 warps (warp tile 64x64), 4-stage
// mbarrier pipeline. Fragment addressing identical to the numerically
// verified R3/R4 mapping.
// ---------------------------------------------------------------------------
__device__ __forceinline__ uint32_t smem_u32(const void* p) {
    uint32_t a;
    asm("{ .reg .u64 t; cvta.to.shared.u64 t, %1; cvt.u32.u64 %0, t; }" : "=r"(a) : "l"(p));
    return a;
}
__device__ __forceinline__ void mbar_init(uint32_t a, uint32_t c) {
    asm volatile("mbarrier.init.shared.b64 [%0], %1;" :: "r"(a), "r"(c) : "memory");
}
__device__ __forceinline__ void mbar_expect_tx(uint32_t a, uint32_t tx) {
    asm volatile("mbarrier.arrive.expect_tx.shared::cta.b64 _, [%0], %1;"
                 :: "r"(a), "r"(tx) : "memory");
}
__device__ __forceinline__ void bulk_g2s(uint32_t dst, const void* src, uint32_t bytes,
                                         uint32_t mbar) {
    asm volatile(
        "cp.async.bulk.shared::cta.global.mbarrier::complete_tx::bytes [%0], [%1], %2, [%3];"
        :: "r"(dst), "l"(src), "r"(bytes), "r"(mbar) : "memory");
}
__device__ __forceinline__ void mbar_wait(uint32_t a, uint32_t ph) {
    asm volatile(
        "{\n .reg .pred P;\n"
        "WL_%=:\n"
        " mbarrier.try_wait.parity.acquire.cta.shared::cta.b64 P, [%0], %1;\n"
        " @P bra.uni WD_%=;\n"
        " bra.uni WL_%=;\n"
        "WD_%=:\n}" :: "r"(a), "r"(ph) : "memory");
}
__device__ __forceinline__ void ldm_x4(uint32_t& r0, uint32_t& r1, uint32_t& r2,
                                       uint32_t& r3, uint32_t addr) {
    asm volatile("ldmatrix.sync.aligned.m8n8.x4.shared.b16 {%0,%1,%2,%3}, [%4];"
                 : "=r"(r0), "=r"(r1), "=r"(r2), "=r"(r3) : "r"(addr));
}

__global__ __launch_bounds__(256, 1) void gemm_hmma_kernel(const float* __restrict__ wscale,
                                                           const float* __restrict__ bias,
                                                           float* __restrict__ out) {
    extern __shared__ char smem[];
    uint32_t raw = smem_u32(smem);
    uint32_t sbase = (raw + 1023u) & ~1023u;
    uint32_t barr = sbase + NS * STG;

    const int t = threadIdx.x;
    const int wid = t >> 5;
    const int lane = t & 31;
    const int warpM = wid & 1;
    const int warpN = wid >> 1;

    // tile decode with L2 group swizzle: tiles_m=64, tiles_n=64, GM=8
    int gid = blockIdx.x;
    int grp = gid >> 9;
    int rem = gid & 511;
    int tm = grp * 8 + (rem & 7);
    int tn = rem >> 3;

    const char* gA = (const char*)g_qa + ((size_t)tm * NKT << 14);
    const char* gB = (const char*)g_wb + ((size_t)tn * NKT << 15);

    if (t == 0) {
#pragma unroll
        for (int s = 0; s < NS; s++) mbar_init(barr + 8 * s, 1);
    }
    __syncthreads();

    auto issue = [&](int buf, int kt) {
        uint32_t mb = barr + 8 * buf;
        mbar_expect_tx(mb, STG);
        bulk_g2s(sbase + buf * STG,         gA + ((size_t)kt << 14), STG_A, mb);
        bulk_g2s(sbase + buf * STG + STG_A, gB + ((size_t)kt << 15), STG_B, mb);
    };

    if (t == 0) {
#pragma unroll
        for (int s = 0; s < NS - 1; s++) issue(s, s);
    }

    float acc[4][8][4];
#pragma unroll
    for (int mf = 0; mf < 4; mf++)
#pragma unroll
        for (int nf = 0; nf < 8; nf++)
#pragma unroll
            for (int i = 0; i < 4; i++) acc[mf][nf][i] = 0.0f;

    const int seg = lane >> 3;                   // matrix id 0..3
    const int lrow = lane & 7;
    const int a_rb = warpM * 64 + (seg & 1) * 8 + lrow;   // + mf*16
    const int b_rb = warpN * 64 + (seg & 1) * 8 + lrow;   // + nf2*16
    const int cseg = seg >> 1;                   // 16B chunk within k16: + 2*ks

    for (int kt = 0; kt < NKT; kt++) {
        int s = kt & (NS - 1);
        mbar_wait(barr + 8 * s, (kt >> 2) & 1);

        uint32_t sA = sbase + s * STG;
        uint32_t sB = sA + STG_A;

#pragma unroll
        for (int ks = 0; ks < 4; ks++) {         // 4 x k16 per 64-elem stage
            const int chunk = cseg + 2 * ks;
            uint32_t a[4][4], b[8][2];
#pragma unroll
            for (int mf = 0; mf < 4; mf++) {
                int r = a_rb + mf * 16;
                ldm_x4(a[mf][0], a[mf][1], a[mf][2], a[mf][3],
                       sA + r * 128 + ((chunk ^ (r & 7)) << 4));
            }
#pragma unroll
            for (int nf2 = 0; nf2 < 4; nf2++) {
                int r = b_rb + nf2 * 16;
                uint32_t r0, r1, r2, r3;
                ldm_x4(r0, r1, r2, r3, sB + r * 128 + ((chunk ^ (r & 7)) << 4));
                b[nf2 * 2][0] = r0; b[nf2 * 2][1] = r2;
                b[nf2 * 2 + 1][0] = r1; b[nf2 * 2 + 1][1] = r3;
            }
#pragma unroll
            for (int mf = 0; mf < 4; mf++)
#pragma unroll
                for (int nf = 0; nf < 8; nf++)
                    asm volatile(
                        "mma.sync.aligned.m16n8k16.row.col.f32.bf16.bf16.f32 "
                        "{%0,%1,%2,%3}, {%4,%5,%6,%7}, {%8,%9}, {%0,%1,%2,%3};\n"
                        : "+f"(acc[mf][nf][0]), "+f"(acc[mf][nf][1]),
                          "+f"(acc[mf][nf][2]), "+f"(acc[mf][nf][3])
                        : "r"(a[mf][0]), "r"(a[mf][1]), "r"(a[mf][2]), "r"(a[mf][3]),
                          "r"(b[nf][0]), "r"(b[nf][1]));
        }

        __syncthreads();
        int nk = kt + NS - 1;
        if (t == 0 && nk < NKT) issue(nk & (NS - 1), nk);
    }

    // epilogue: dequant + bias (acc holds exact integer values in f32)
    const int tig = lane & 3;
    const int gID = lane >> 2;
#pragma unroll
    for (int mf = 0; mf < 4; mf++) {
        int r0 = tm * BM + warpM * 64 + mf * 16 + gID;
        float sx0 = g_sx[r0];
        float sx1 = g_sx[r0 + 8];
        float* o0 = out + (size_t)r0 * N_DIM + tn * BN;
        float* o1 = o0 + (size_t)8 * N_DIM;
#pragma unroll
        for (int nf = 0; nf < 8; nf++) {
            int c = warpN * 64 + nf * 8 + tig * 2;
            float w0 = __ldg(wscale + tn * BN + c);
            float w1 = __ldg(wscale + tn * BN + c + 1);
            float b0 = __ldg(bias + tn * BN + c);
            float b1 = __ldg(bias + tn * BN + c + 1);
            float2 v0, v1;
            v0.x = acc[mf][nf][0] * sx0 * w0 + b0;
            v0.y = acc[mf][nf][1] * sx0 * w1 + b1;
            v1.x = acc[mf][nf][2] * sx1 * w0 + b0;
            v1.y = acc[mf][nf][3] * sx1 * w1 + b1;
            *(float2*)(o0 + c) = v0;
            *(float2*)(o1 + c) = v1;
        }
    }
}

// ---------------------------------------------------------------------------
extern "C" void kernel_launch(void* const* d_in, const int* in_sizes, int n_in,
                              void* d_out, int out_size) {
    (void)in_sizes; (void)n_in; (void)out_size;
    const float* x      = (const float*)d_in[0];
    const int*   wq     = (const int*)d_in[1];
    const float* wscale = (const float*)d_in[2];
    const float* bias   = (const float*)d_in[3];
    float* out = (float*)d_out;

    quant_rows_kernel<<<M_DIM, 256>>>(x);
    convert_w_kernel<<<N_DIM, 256>>>(wq);

    cudaFuncSetAttribute(gemm_hmma_kernel, cudaFuncAttributeMaxDynamicSharedMemorySize,
                         SMEM_TOTAL);
    int gemm_blocks = (M_DIM / BM) * (N_DIM / BN);   // 4096
    gemm_hmma_kernel<<<gemm_blocks, 256, SMEM_TOTAL>>>(wscale, bias, out);
}